// round 3
// baseline (speedup 1.0000x reference)
#include <cuda_runtime.h>

#define B_  32
#define S_  64
#define T_  32
#define H_  512
#define V_  32000
#define K3  1536

typedef unsigned long long ull;

// ---------------- device scratch ----------------
__device__ float g_Ukeys[B_ * S_ * H_];
__device__ float g_query[2][1024 * B_];   // [(l*512+h)][b], double buffered
__device__ float g_ctxT[512 * B_];        // context transposed [h][b]
__device__ float g_sc[B_ * S_];           // attention scores
__device__ float g_qp[4][H_ * B_];
__device__ float g_gh0p[2][K3 * B_];
__device__ float g_gh1p[2][K3 * B_];
__device__ float g_gi0p[4][K3 * B_];
__device__ float g_gi1p[2][K3 * B_];
__device__ float g_logits[B_ * V_];
__device__ float g_pm[B_ * 250];
__device__ float g_ps[B_ * 250];
__device__ int   g_pi[B_ * 250];
__device__ float g_lse[B_];
__device__ int   g_tok[B_];

// ---------------- packed f32x2 helpers ----------------
__device__ __forceinline__ ull pk2(float a, float b) {
    ull r; asm("mov.b64 %0, {%1,%2};" : "=l"(r) : "f"(a), "f"(b)); return r;
}
__device__ __forceinline__ ull fma2(ull a, ull b, ull c) {
    ull d; asm("fma.rn.f32x2 %0, %1, %2, %3;" : "=l"(d) : "l"(a), "l"(b), "l"(c)); return d;
}
__device__ __forceinline__ void upk(ull v, float& lo, float& hi) {
    asm("mov.b64 {%0,%1}, %2;" : "=f"(lo), "=f"(hi) : "l"(v));
}
__device__ __forceinline__ float tanh_ap(float x) {
    float y; asm("tanh.approx.f32 %0, %1;" : "=f"(y) : "f"(x)); return y;
}

// ---------------- GEMM core: 128 threads, C[m0..+127][0..31] += W[.,k0..+255] @ Xs ----------------
// W must be pre-offset by k0. Xs: [256][32] floats.
__device__ __forceinline__ void gemm_core(
    const float* __restrict__ W, int ldW,
    float* __restrict__ C, int m0, const float* Xs)
{
    int tid = threadIdx.x;
    int bt = tid & 3, mt = tid >> 2;
    int b0 = bt * 8;
    const float* wr0 = W + (size_t)(m0 + mt) * ldW;

    ull acc[4][4];
    #pragma unroll
    for (int i = 0; i < 4; i++)
        #pragma unroll
        for (int j = 0; j < 4; j++) acc[i][j] = 0ULL;

    for (int kk = 0; kk < 256; kk += 4) {
        float4 w[4];
        #pragma unroll
        for (int i = 0; i < 4; i++)
            w[i] = *(const float4*)(wr0 + (size_t)i * 32 * ldW + kk);
        #pragma unroll
        for (int c = 0; c < 4; c++) {
            ull xp[4];
            #pragma unroll
            for (int j = 0; j < 4; j++)
                xp[j] = *(const ull*)&Xs[(kk + c) * 32 + b0 + 2 * j];
            #pragma unroll
            for (int i = 0; i < 4; i++) {
                const float* wf = reinterpret_cast<const float*>(&w[i]);
                ull wd = pk2(wf[c], wf[c]);
                #pragma unroll
                for (int j = 0; j < 4; j++) acc[i][j] = fma2(wd, xp[j], acc[i][j]);
            }
        }
    }
    #pragma unroll
    for (int i = 0; i < 4; i++)
        #pragma unroll
        for (int j = 0; j < 4; j++)
            *(ull*)&C[(size_t)(m0 + mt + i * 32) * 32 + b0 + 2 * j] = acc[i][j];
}

__device__ __forceinline__ void stage_linear(const float* __restrict__ Xchunk, float* Xs) {
    int tid = threadIdx.x;
    const float4* src = (const float4*)Xchunk;
    float4* dst = (float4*)Xs;
    #pragma unroll
    for (int i = 0; i < 16; i++) dst[tid + 128 * i] = src[tid + 128 * i];
}

// ---------------- init ----------------
__global__ void k_init(const float* __restrict__ ehid) {
    int idx = blockIdx.x * 256 + threadIdx.x;   // 32768
    int row = idx >> 5, b = idx & 31;
    int l = row >> 9, h = row & 511;
    g_query[0][row * 32 + b] = ehid[((size_t)l * 32 + b) * 512 + h];
    if (idx < B_) g_tok[idx] = 1;  // BOS
}

// ---------------- Ukeys = enc @ Ua^T + bua ----------------
__global__ __launch_bounds__(256) void k_ukeys(
    const float* __restrict__ enc, const float* __restrict__ Ua,
    const float* __restrict__ bua)
{
    __shared__ float es[8 * 512];
    int row0 = blockIdx.x * 8;   // grid 256
    int tid = threadIdx.x;
    {
        const float4* src = (const float4*)(enc + (size_t)row0 * 512);
        #pragma unroll
        for (int i = 0; i < 4; i++) ((float4*)es)[tid + 256 * i] = src[tid + 256 * i];
    }
    __syncthreads();
    int h = tid;
    float acc0[8], acc1[8];
    #pragma unroll
    for (int r = 0; r < 8; r++) { acc0[r] = 0.f; acc1[r] = 0.f; }
    const float* u0 = Ua + (size_t)h * 512;
    const float* u1 = Ua + (size_t)(h + 256) * 512;
    for (int k = 0; k < 512; k++) {
        float w0 = u0[k], w1 = u1[k];
        #pragma unroll
        for (int r = 0; r < 8; r++) {
            float x = es[r * 512 + k];
            acc0[r] += w0 * x; acc1[r] += w1 * x;
        }
    }
    float bb0 = bua[h], bb1 = bua[h + 256];
    #pragma unroll
    for (int r = 0; r < 8; r++) {
        g_Ukeys[(size_t)(row0 + r) * 512 + h]       = acc0[r] + bb0;
        g_Ukeys[(size_t)(row0 + r) * 512 + h + 256] = acc1[r] + bb1;
    }
}

// ---------------- pre-GEMMs: q, Gh0, Gh1 (reads h_prev) ----------------
__global__ __launch_bounds__(128) void k_pre3(
    const float* __restrict__ Wa, const float* __restrict__ Whh0,
    const float* __restrict__ Whh1, int par)
{
    __shared__ float Xs[8192];
    const float* qprev = (const float*)g_query[par];
    int blk = blockIdx.x;
    if (blk < 16) {                 // q: M=512, K=1024
        int mt = blk >> 2, ks = blk & 3;
        stage_linear(qprev + ks * 8192, Xs);
        __syncthreads();
        gemm_core(Wa + ks * 256, 1024, g_qp[ks], mt * 128, Xs);
    } else if (blk < 40) {          // Gh0: M=1536, K=512 (X = h0_prev)
        int tt = blk - 16; int mt = tt >> 1, ks = tt & 1;
        stage_linear(qprev + ks * 8192, Xs);
        __syncthreads();
        gemm_core(Whh0 + ks * 256, 512, g_gh0p[ks], mt * 128, Xs);
    } else {                        // Gh1: X = h1_prev
        int tt = blk - 40; int mt = tt >> 1, ks = tt & 1;
        stage_linear(qprev + 512 * 32 + ks * 8192, Xs);
        __syncthreads();
        gemm_core(Whh1 + ks * 256, 512, g_gh1p[ks], mt * 128, Xs);
    }
}

// ---------------- scores: tanh attention energies, 256 blocks ----------------
__global__ __launch_bounds__(128) void k_scores(
    const float* __restrict__ Va, const float* __restrict__ ba,
    const float* __restrict__ bva)
{
    int blk = blockIdx.x;              // 256 = 32 b x 8 s-chunks
    int b = blk >> 3, sc8 = blk & 7;
    __shared__ float qs[512], vas[512];
    int tid = threadIdx.x;
    for (int h = tid; h < 512; h += 128) {
        qs[h] = g_qp[0][h * 32 + b] + g_qp[1][h * 32 + b]
              + g_qp[2][h * 32 + b] + g_qp[3][h * 32 + b] + ba[h];
        vas[h] = Va[h];
    }
    __syncthreads();
    int wid = tid >> 5, lane = tid & 31;
    #pragma unroll
    for (int si = wid; si < 8; si += 4) {
        int s = sc8 * 8 + si;
        const float* uk = g_Ukeys + ((size_t)(b * 64 + s)) * 512;
        float acc = 0.f;
        for (int h = lane; h < 512; h += 32)
            acc += vas[h] * tanh_ap(qs[h] + uk[h]);
        #pragma unroll
        for (int o = 16; o; o >>= 1) acc += __shfl_xor_sync(0xffffffffu, acc, o);
        if (lane == 0) g_sc[b * 64 + s] = acc + bva[0];
    }
}

// ---------------- attn2: softmax + context -> g_ctxT + attn weights ----------------
__global__ __launch_bounds__(256) void k_attn2(
    const float* __restrict__ enc, float* __restrict__ attn_out, int t)
{
    int b = blockIdx.x, tid = threadIdx.x;
    __shared__ float ws[64];
    if (tid < 32) {
        float v0 = g_sc[b * 64 + tid], v1 = g_sc[b * 64 + 32 + tid];
        float m = fmaxf(v0, v1);
        #pragma unroll
        for (int o = 16; o; o >>= 1) m = fmaxf(m, __shfl_xor_sync(0xffffffffu, m, o));
        float e0 = __expf(v0 - m), e1 = __expf(v1 - m);
        float s = e0 + e1;
        #pragma unroll
        for (int o = 16; o; o >>= 1) s += __shfl_xor_sync(0xffffffffu, s, o);
        float inv = 1.f / s;
        ws[tid] = e0 * inv; ws[32 + tid] = e1 * inv;
    }
    __syncthreads();
    if (attn_out && tid < 64)
        attn_out[((size_t)b * T_ + t) * 64 + tid] = ws[tid];
    for (int h = tid; h < 512; h += 256) {
        float c = 0.f;
        const float* e = enc + ((size_t)b * 64) * 512 + h;
        #pragma unroll 8
        for (int s = 0; s < 64; s++) c += ws[s] * e[(size_t)s * 512];
        g_ctxT[h * 32 + b] = c;
    }
}

// ---------------- gi0: Wih0 @ [emb(tok); context], emb gather fused in staging ----------------
__global__ __launch_bounds__(128) void k_gi0emb(
    const float* __restrict__ W0ih, const float* __restrict__ emb)
{
    __shared__ float Xs[8192];
    int blk = blockIdx.x;           // 48 = 12 mtiles x 4 ks
    int mt = blk >> 2, ks = blk & 3;
    int tid = threadIdx.x;
    if (ks < 2) {
        int b = tid & 31, seg = tid >> 5;   // 4 segs x 64 k
        int tok = g_tok[b];
        const float* er = emb + (size_t)tok * 512 + ks * 256 + seg * 64;
        #pragma unroll
        for (int i = 0; i < 16; i++) {
            float4 v = *(const float4*)(er + i * 4);
            int k = seg * 64 + i * 4;
            Xs[(k + 0) * 32 + b] = v.x; Xs[(k + 1) * 32 + b] = v.y;
            Xs[(k + 2) * 32 + b] = v.z; Xs[(k + 3) * 32 + b] = v.w;
        }
    } else {
        stage_linear(g_ctxT + (ks - 2) * 8192, Xs);
    }
    __syncthreads();
    gemm_core(W0ih + ks * 256, 1024, g_gi0p[ks], mt * 128, Xs);
}

// ---------------- gi1: Wih1 @ h0 ----------------
__global__ __launch_bounds__(128) void k_gi1(const float* __restrict__ W1ih, int par1)
{
    __shared__ float Xs[8192];
    int blk = blockIdx.x;   // 24 = 12 mtiles x 2 ks
    int mt = blk >> 1, ks = blk & 1;
    stage_linear((const float*)g_query[par1] + ks * 8192, Xs);
    __syncthreads();
    gemm_core(W1ih + ks * 256, 512, g_gi1p[ks], mt * 128, Xs);
}

// ---------------- GRU gate combine ----------------
__global__ __launch_bounds__(256) void k_comb(
    int layer, int par, const float* __restrict__ bih, const float* __restrict__ bhh)
{
    int idx = blockIdx.x * 256 + threadIdx.x;   // 16384
    int j = idx >> 5, b = idx & 31;
    int o_r = j * 32 + b, o_z = (j + 512) * 32 + b, o_n = (j + 1024) * 32 + b;
    float gir, giz, gin_, ghr, ghz, ghn, hp;
    if (layer == 0) {
        gir  = g_gi0p[0][o_r] + g_gi0p[1][o_r] + g_gi0p[2][o_r] + g_gi0p[3][o_r];
        giz  = g_gi0p[0][o_z] + g_gi0p[1][o_z] + g_gi0p[2][o_z] + g_gi0p[3][o_z];
        gin_ = g_gi0p[0][o_n] + g_gi0p[1][o_n] + g_gi0p[2][o_n] + g_gi0p[3][o_n];
        ghr = g_gh0p[0][o_r] + g_gh0p[1][o_r];
        ghz = g_gh0p[0][o_z] + g_gh0p[1][o_z];
        ghn = g_gh0p[0][o_n] + g_gh0p[1][o_n];
        hp = g_query[par][j * 32 + b];
    } else {
        gir  = g_gi1p[0][o_r] + g_gi1p[1][o_r];
        giz  = g_gi1p[0][o_z] + g_gi1p[1][o_z];
        gin_ = g_gi1p[0][o_n] + g_gi1p[1][o_n];
        ghr = g_gh1p[0][o_r] + g_gh1p[1][o_r];
        ghz = g_gh1p[0][o_z] + g_gh1p[1][o_z];
        ghn = g_gh1p[0][o_n] + g_gh1p[1][o_n];
        hp = g_query[par][(512 + j) * 32 + b];
    }
    gir += bih[j];         ghr += bhh[j];
    giz += bih[j + 512];   ghz += bhh[j + 512];
    gin_ += bih[j + 1024]; ghn += bhh[j + 1024];
    float r = 1.f / (1.f + expf(-(gir + ghr)));
    float z = 1.f / (1.f + expf(-(giz + ghz)));
    float n = tanhf(gin_ + r * ghn);
    float h = (1.f - z) * n + z * hp;
    int off = layer ? 512 : 0;
    g_query[par ^ 1][(off + j) * 32 + b] = h;
}

// ---------------- logits + fused softmax partials ----------------
__global__ __launch_bounds__(128) void k_logits(
    const float* __restrict__ outW, const float* __restrict__ outb, int parN)
{
    __shared__ float Xs[8192];
    int tid = threadIdx.x;
    int bt = tid & 3, mt = tid >> 2;
    int b0 = bt * 8;
    int v0 = blockIdx.x * 128;   // grid 250
    ull acc[4][4];
    #pragma unroll
    for (int i = 0; i < 4; i++)
        #pragma unroll
        for (int j = 0; j < 4; j++) acc[i][j] = 0ULL;

    const float* h1T = (const float*)g_query[parN] + 512 * 32;
    for (int ck = 0; ck < 2; ck++) {
        if (ck) __syncthreads();
        stage_linear(h1T + ck * 8192, Xs);
        __syncthreads();
        const float* wr0 = outW + (size_t)(v0 + mt) * 512 + ck * 256;
        for (int kk = 0; kk < 256; kk += 4) {
            float4 w[4];
            #pragma unroll
            for (int i = 0; i < 4; i++)
                w[i] = *(const float4*)(wr0 + (size_t)i * 32 * 512 + kk);
            #pragma unroll
            for (int c = 0; c < 4; c++) {
                ull xp[4];
                #pragma unroll
                for (int j = 0; j < 4; j++)
                    xp[j] = *(const ull*)&Xs[(kk + c) * 32 + b0 + 2 * j];
                #pragma unroll
                for (int i = 0; i < 4; i++) {
                    const float* wf = reinterpret_cast<const float*>(&w[i]);
                    ull wd = pk2(wf[c], wf[c]);
                    #pragma unroll
                    for (int j = 0; j < 4; j++) acc[i][j] = fma2(wd, xp[j], acc[i][j]);
                }
            }
        }
    }
    // unpack + bias + store logits
    float lv[8][4];
    #pragma unroll
    for (int i = 0; i < 4; i++) {
        int v = v0 + mt + i * 32;
        float bb = outb[v];
        #pragma unroll
        for (int j = 0; j < 4; j++) {
            float lo, hi; upk(acc[i][j], lo, hi);
            lv[2 * j][i] = lo + bb; lv[2 * j + 1][i] = hi + bb;
            g_logits[(size_t)(b0 + 2 * j) * V_ + v]     = lo + bb;
            g_logits[(size_t)(b0 + 2 * j + 1) * V_ + v] = hi + bb;
        }
    }
    __syncthreads();
    // softmax partials per (b, block): max, argmax (first-idx tie), sum exp
    float* sm_m = Xs;
    float* sm_s = Xs + 1024;
    int*   sm_i = (int*)(Xs + 2048);
    #pragma unroll
    for (int jj = 0; jj < 8; jj++) {
        int b = b0 + jj;
        float m = lv[jj][0]; int id = v0 + mt;
        #pragma unroll
        for (int i = 1; i < 4; i++) {
            float x = lv[jj][i];
            if (x > m) { m = x; id = v0 + mt + i * 32; }
        }
        float s = 0.f;
        #pragma unroll
        for (int i = 0; i < 4; i++) s += __expf(lv[jj][i] - m);
        sm_m[b * 32 + mt] = m; sm_s[b * 32 + mt] = s; sm_i[b * 32 + mt] = id;
    }
    __syncthreads();
    if (tid < 32) {
        int b = tid;
        float m = sm_m[b * 32], s = sm_s[b * 32];
        int id = sm_i[b * 32];
        for (int q = 1; q < 32; q++) {
            float mq = sm_m[b * 32 + q], sq = sm_s[b * 32 + q];
            int iq = sm_i[b * 32 + q];
            if (mq > m || (mq == m && iq < id)) {
                s = s * __expf(m - mq) + sq; m = mq; id = iq;
            } else {
                s += sq * __expf(mq - m);
            }
        }
        g_pm[b * 250 + blockIdx.x] = m;
        g_ps[b * 250 + blockIdx.x] = s;
        g_pi[b * 250 + blockIdx.x] = id;
    }
}

// ---------------- softmax finalize: combine 250 partials -> tok, lse ----------------
__global__ __launch_bounds__(256) void k_smfin()
{
    int b = blockIdx.x, tid = threadIdx.x;
    __shared__ float rm[256], rs[256];
    __shared__ int ri[256];
    float m = -1e30f, s = 0.f; int id = 0x7fffffff;
    if (tid < 250) { m = g_pm[b * 250 + tid]; s = g_ps[b * 250 + tid]; id = g_pi[b * 250 + tid]; }
    rm[tid] = m; rs[tid] = s; ri[tid] = id;
    __syncthreads();
    for (int o = 128; o; o >>= 1) {
        if (tid < o) {
            float mq = rm[tid + o], sq = rs[tid + o];
            int iq = ri[tid + o];
            float mm = rm[tid];
            if (mq > mm || (mq == mm && iq < ri[tid])) {
                rs[tid] = rs[tid] * __expf(mm - mq) + sq; rm[tid] = mq; ri[tid] = iq;
            } else {
                rs[tid] += sq * __expf(mq - mm);
            }
        }
        __syncthreads();
    }
    if (tid == 0) { g_tok[b] = ri[0]; g_lse[b] = logf(rs[0]) + rm[0]; }
}

// ---------------- write log_probs ----------------
__global__ __launch_bounds__(256) void k_smwrite(float* __restrict__ lp, int t)
{
    int b = blockIdx.x >> 3, c = blockIdx.x & 7;   // grid 256
    float lse = g_lse[b];
    const float* lg = g_logits + (size_t)b * V_;
    float* o = lp + ((size_t)b * T_ + t) * V_;
    for (int v = c * 4000 + threadIdx.x; v < (c + 1) * 4000; v += 256)
        o[v] = lg[v] - lse;
}

// ---------------- final hidden out ----------------
__global__ void k_hidout(float* __restrict__ hid) {
    int idx = blockIdx.x * 256 + threadIdx.x;   // 32768
    int row = idx >> 5, b = idx & 31;
    int l = row >> 9, h = row & 511;
    hid[((size_t)l * 32 + b) * 512 + h] = g_query[0][row * 32 + b];
}

// ---------------- launcher ----------------
extern "C" void kernel_launch(void* const* d_in, const int* in_sizes, int n_in,
                              void* d_out, int out_size)
{
    const float* enc  = (const float*)d_in[0];
    const float* ehid = (const float*)d_in[1];
    const float* emb  = (const float*)d_in[3];
    const float* Wa   = (const float*)d_in[4];
    const float* ba   = (const float*)d_in[5];
    const float* Ua   = (const float*)d_in[6];
    const float* bua  = (const float*)d_in[7];
    const float* Va   = (const float*)d_in[8];
    const float* bva  = (const float*)d_in[9];
    const float* W0ih = (const float*)d_in[10];
    const float* W0hh = (const float*)d_in[11];
    const float* b0ih = (const float*)d_in[12];
    const float* b0hh = (const float*)d_in[13];
    const float* W1ih = (const float*)d_in[14];
    const float* W1hh = (const float*)d_in[15];
    const float* b1ih = (const float*)d_in[16];
    const float* b1hh = (const float*)d_in[17];
    const float* outW = (const float*)d_in[18];
    const float* outb = (const float*)d_in[19];

    float* out = (float*)d_out;
    const long long NLP  = (long long)B_ * T_ * V_;
    const long long NHID = 2LL * B_ * H_;
    const long long NATT = (long long)B_ * T_ * S_;
    bool full = (long long)out_size >= NLP + NHID + NATT;
    float* lp   = out;
    float* hid  = full ? out + NLP : nullptr;
    float* attn = full ? out + NLP + NHID : nullptr;

    static cudaStream_t sB = 0, sC = 0;
    static cudaEvent_t Eh = 0, Ec = 0, Ef = 0, Ew = 0;
    if (!sB) {
        cudaStreamCreateWithFlags(&sB, cudaStreamNonBlocking);
        cudaStreamCreateWithFlags(&sC, cudaStreamNonBlocking);
        cudaEventCreateWithFlags(&Eh, cudaEventDisableTiming);
        cudaEventCreateWithFlags(&Ec, cudaEventDisableTiming);
        cudaEventCreateWithFlags(&Ef, cudaEventDisableTiming);
        cudaEventCreateWithFlags(&Ew, cudaEventDisableTiming);
    }

    k_init<<<128, 256>>>(ehid);
    k_ukeys<<<256, 256>>>(enc, Ua, bua);

    // attention prep for t = 0 on stream B
    cudaEventRecord(Eh, 0);
    cudaStreamWaitEvent(sB, Eh, 0);
    k_pre3<<<64, 128, 0, sB>>>(Wa, W0hh, W1hh, 0);
    k_scores<<<256, 128, 0, sB>>>(Va, ba, bva);
    k_attn2<<<32, 256, 0, sB>>>(enc, attn, 0);
    cudaEventRecord(Ec, sB);

    for (int t = 0; t < T_; t++) {
        int p = t & 1;
        // GRU chain (needs context(t) from B and tok(t-1) from smfin)
        cudaStreamWaitEvent(0, Ec, 0);
        k_gi0emb<<<48, 128>>>(W0ih, emb);
        k_comb<<<64, 256>>>(0, p, b0ih, b0hh);
        k_gi1<<<24, 128>>>(W1ih, p ^ 1);
        k_comb<<<64, 256>>>(1, p, b1ih, b1hh);
        cudaEventRecord(Eh, 0);

        // attention prep for step t+1 overlaps with logits/softmax
        if (t < T_ - 1) {
            cudaStreamWaitEvent(sB, Eh, 0);
            k_pre3<<<64, 128, 0, sB>>>(Wa, W0hh, W1hh, p ^ 1);
            k_scores<<<256, 128, 0, sB>>>(Va, ba, bva);
            k_attn2<<<32, 256, 0, sB>>>(enc, attn, t + 1);
            cudaEventRecord(Ec, sB);
        }

        // logits + softmax (main). Protect g_logits from in-flight smwrite(t-1).
        if (t > 0) cudaStreamWaitEvent(0, Ew, 0);
        k_logits<<<250, 128>>>(outW, outb, p ^ 1);
        k_smfin<<<32, 256>>>();
        cudaEventRecord(Ef, 0);
        cudaStreamWaitEvent(sC, Ef, 0);
        k_smwrite<<<256, 256, 0, sC>>>(lp, t);
        cudaEventRecord(Ew, sC);
    }

    cudaStreamWaitEvent(0, Ew, 0);
    if (hid) k_hidout<<<128, 256>>>(hid);
    else     k_hidout<<<1, 1>>>(nullptr);   // keep join node shape; never taken in practice
}

// round 5
// speedup vs baseline: 1.1458x; 1.1458x over previous
#include <cuda_runtime.h>

#define B_  32
#define S_  64
#define T_  32
#define H_  512
#define V_  32000
#define K3  1536

typedef unsigned long long ull;

// ---------------- device scratch ----------------
__device__ float g_Ukeys[B_ * S_ * H_];
__device__ float g_query[2][1024 * B_];   // [(l*512+h)][b], double buffered
__device__ float g_ctxT[512 * B_];        // context transposed [h][b]
__device__ float g_sc[B_ * S_];           // attention scores
__device__ float g_qp[4][H_ * B_];
__device__ float g_gh0p[2][K3 * B_];
__device__ float g_gh1p[2][K3 * B_];
__device__ float g_gi0p[4][K3 * B_];
__device__ float g_gi1p[2][K3 * B_];
__device__ float g_logits[B_ * V_];
__device__ float g_pm[B_ * 250];
__device__ float g_ps[B_ * 250];
__device__ int   g_pi[B_ * 250];
__device__ int   g_tok[B_];

// ---------------- packed f32x2 helpers ----------------
__device__ __forceinline__ ull pk2(float a, float b) {
    ull r; asm("mov.b64 %0, {%1,%2};" : "=l"(r) : "f"(a), "f"(b)); return r;
}
__device__ __forceinline__ ull fma2(ull a, ull b, ull c) {
    ull d; asm("fma.rn.f32x2 %0, %1, %2, %3;" : "=l"(d) : "l"(a), "l"(b), "l"(c)); return d;
}
__device__ __forceinline__ void upk(ull v, float& lo, float& hi) {
    asm("mov.b64 {%0,%1}, %2;" : "=f"(lo), "=f"(hi) : "l"(v));
}
__device__ __forceinline__ float tanh_ap(float x) {
    float y; asm("tanh.approx.f32 %0, %1;" : "=f"(y) : "f"(x)); return y;
}

// ---------------- GEMM core: 128 threads ----------------
__device__ __forceinline__ void gemm_core(
    const float* __restrict__ W, int ldW,
    float* __restrict__ C, int m0, const float* Xs)
{
    int tid = threadIdx.x;
    int bt = tid & 3, mt = tid >> 2;
    int b0 = bt * 8;
    const float* wr0 = W + (size_t)(m0 + mt) * ldW;

    ull acc[4][4];
    #pragma unroll
    for (int i = 0; i < 4; i++)
        #pragma unroll
        for (int j = 0; j < 4; j++) acc[i][j] = 0ULL;

    for (int kk = 0; kk < 256; kk += 4) {
        float4 w[4];
        #pragma unroll
        for (int i = 0; i < 4; i++)
            w[i] = *(const float4*)(wr0 + (size_t)i * 32 * ldW + kk);
        #pragma unroll
        for (int c = 0; c < 4; c++) {
            ull xp[4];
            #pragma unroll
            for (int j = 0; j < 4; j++)
                xp[j] = *(const ull*)&Xs[(kk + c) * 32 + b0 + 2 * j];
            #pragma unroll
            for (int i = 0; i < 4; i++) {
                const float* wf = reinterpret_cast<const float*>(&w[i]);
                ull wd = pk2(wf[c], wf[c]);
                #pragma unroll
                for (int j = 0; j < 4; j++) acc[i][j] = fma2(wd, xp[j], acc[i][j]);
            }
        }
    }
    #pragma unroll
    for (int i = 0; i < 4; i++)
        #pragma unroll
        for (int j = 0; j < 4; j++)
            *(ull*)&C[(size_t)(m0 + mt + i * 32) * 32 + b0 + 2 * j] = acc[i][j];
}

__device__ __forceinline__ void stage_linear(const float* __restrict__ Xchunk, float* Xs) {
    int tid = threadIdx.x;
    const float4* src = (const float4*)Xchunk;
    float4* dst = (float4*)Xs;
    #pragma unroll
    for (int i = 0; i < 16; i++) dst[tid + 128 * i] = src[tid + 128 * i];
}

// ---------------- init ----------------
__global__ void k_init(const float* __restrict__ ehid) {
    int idx = blockIdx.x * 256 + threadIdx.x;   // 32768
    int row = idx >> 5, b = idx & 31;
    int l = row >> 9, h = row & 511;
    g_query[0][row * 32 + b] = ehid[((size_t)l * 32 + b) * 512 + h];
    if (idx < B_) g_tok[idx] = 1;  // BOS
}

// ---------------- Ukeys = enc @ Ua^T + bua ----------------
__global__ __launch_bounds__(256) void k_ukeys(
    const float* __restrict__ enc, const float* __restrict__ Ua,
    const float* __restrict__ bua)
{
    __shared__ float es[8 * 512];
    int row0 = blockIdx.x * 8;   // grid 256
    int tid = threadIdx.x;
    {
        const float4* src = (const float4*)(enc + (size_t)row0 * 512);
        #pragma unroll
        for (int i = 0; i < 4; i++) ((float4*)es)[tid + 256 * i] = src[tid + 256 * i];
    }
    __syncthreads();
    int h = tid;
    float acc0[8], acc1[8];
    #pragma unroll
    for (int r = 0; r < 8; r++) { acc0[r] = 0.f; acc1[r] = 0.f; }
    const float* u0 = Ua + (size_t)h * 512;
    const float* u1 = Ua + (size_t)(h + 256) * 512;
    for (int k = 0; k < 512; k++) {
        float w0 = u0[k], w1 = u1[k];
        #pragma unroll
        for (int r = 0; r < 8; r++) {
            float x = es[r * 512 + k];
            acc0[r] += w0 * x; acc1[r] += w1 * x;
        }
    }
    float bb0 = bua[h], bb1 = bua[h + 256];
    #pragma unroll
    for (int r = 0; r < 8; r++) {
        g_Ukeys[(size_t)(row0 + r) * 512 + h]       = acc0[r] + bb0;
        g_Ukeys[(size_t)(row0 + r) * 512 + h + 256] = acc1[r] + bb1;
    }
}

// ---------------- k_q: q = Wa @ hcat (16 tiles) ----------------
__global__ __launch_bounds__(128) void k_q(const float* __restrict__ Wa, int par)
{
    __shared__ float Xs[8192];
    int mt = blockIdx.x >> 2, ks = blockIdx.x & 3;   // grid 16
    stage_linear((const float*)g_query[par] + ks * 8192, Xs);
    __syncthreads();
    gemm_core(Wa + ks * 256, 1024, g_qp[ks], mt * 128, Xs);
}

// ---------------- scores: tanh attention energies, 256 blocks ----------------
__global__ __launch_bounds__(128) void k_scores(
    const float* __restrict__ Va, const float* __restrict__ ba,
    const float* __restrict__ bva)
{
    int blk = blockIdx.x;              // 256 = 32 b x 8 s-chunks
    int b = blk >> 3, sc8 = blk & 7;
    __shared__ float qs[512], vas[512];
    int tid = threadIdx.x;
    for (int h = tid; h < 512; h += 128) {
        qs[h] = g_qp[0][h * 32 + b] + g_qp[1][h * 32 + b]
              + g_qp[2][h * 32 + b] + g_qp[3][h * 32 + b] + ba[h];
        vas[h] = Va[h];
    }
    __syncthreads();
    int wid = tid >> 5, lane = tid & 31;
    #pragma unroll
    for (int si = wid; si < 8; si += 4) {
        int s = sc8 * 8 + si;
        const float* uk = g_Ukeys + ((size_t)(b * 64 + s)) * 512;
        float acc = 0.f;
        for (int h = lane; h < 512; h += 32)
            acc += vas[h] * tanh_ap(qs[h] + uk[h]);
        #pragma unroll
        for (int o = 16; o; o >>= 1) acc += __shfl_xor_sync(0xffffffffu, acc, o);
        if (lane == 0) g_sc[b * 64 + s] = acc + bva[0];
    }
}

// ---------------- attn2: softmax + context -> g_ctxT + attn weights ----------------
__global__ __launch_bounds__(256) void k_attn2(
    const float* __restrict__ enc, float* __restrict__ attn_out, int t)
{
    int b = blockIdx.x, tid = threadIdx.x;
    __shared__ float ws[64];
    if (tid < 32) {
        float v0 = g_sc[b * 64 + tid], v1 = g_sc[b * 64 + 32 + tid];
        float m = fmaxf(v0, v1);
        #pragma unroll
        for (int o = 16; o; o >>= 1) m = fmaxf(m, __shfl_xor_sync(0xffffffffu, m, o));
        float e0 = __expf(v0 - m), e1 = __expf(v1 - m);
        float s = e0 + e1;
        #pragma unroll
        for (int o = 16; o; o >>= 1) s += __shfl_xor_sync(0xffffffffu, s, o);
        float inv = 1.f / s;
        ws[tid] = e0 * inv; ws[32 + tid] = e1 * inv;
    }
    __syncthreads();
    if (attn_out && tid < 64)
        attn_out[((size_t)b * T_ + t) * 64 + tid] = ws[tid];
    for (int h = tid; h < 512; h += 256) {
        float c = 0.f;
        const float* e = enc + ((size_t)b * 64) * 512 + h;
        #pragma unroll 8
        for (int s = 0; s < 64; s++) c += ws[s] * e[(size_t)s * 512];
        g_ctxT[h * 32 + b] = c;
    }
}

// ---------------- gemmA: gi0 (48 tiles) + gh0 (24) + gh1 (24), 96 blocks ----------------
__global__ __launch_bounds__(128) void k_gemmA(
    const float* __restrict__ W0ih, const float* __restrict__ emb,
    const float* __restrict__ Whh0, const float* __restrict__ Whh1, int par)
{
    __shared__ float Xs[8192];
    int blk = blockIdx.x, tid = threadIdx.x;
    const float* hprev = (const float*)g_query[par];
    if (blk < 48) {               // gi0 = W0ih @ [emb(tok); ctx]
        int mt = blk >> 2, ks = blk & 3;
        if (ks < 2) {
            int b = tid & 31, seg = tid >> 5;
            int tok = g_tok[b];
            const float* er = emb + (size_t)tok * 512 + ks * 256 + seg * 64;
            #pragma unroll
            for (int i = 0; i < 16; i++) {
                float4 v = *(const float4*)(er + i * 4);
                int k = seg * 64 + i * 4;
                Xs[(k + 0) * 32 + b] = v.x; Xs[(k + 1) * 32 + b] = v.y;
                Xs[(k + 2) * 32 + b] = v.z; Xs[(k + 3) * 32 + b] = v.w;
            }
        } else {
            stage_linear(g_ctxT + (ks - 2) * 8192, Xs);
        }
        __syncthreads();
        gemm_core(W0ih + ks * 256, 1024, g_gi0p[ks], mt * 128, Xs);
    } else if (blk < 72) {        // gh0 = Whh0 @ h0_prev
        int tt = blk - 48; int mt = tt >> 1, ks = tt & 1;
        stage_linear(hprev + ks * 8192, Xs);
        __syncthreads();
        gemm_core(Whh0 + ks * 256, 512, g_gh0p[ks], mt * 128, Xs);
    } else {                      // gh1 = Whh1 @ h1_prev
        int tt = blk - 72; int mt = tt >> 1, ks = tt & 1;
        stage_linear(hprev + 512 * 32 + ks * 8192, Xs);
        __syncthreads();
        gemm_core(Whh1 + ks * 256, 512, g_gh1p[ks], mt * 128, Xs);
    }
}

// ---------------- gi1: Wih1 @ h0 ----------------
__global__ __launch_bounds__(128) void k_gi1(const float* __restrict__ W1ih, int par1)
{
    __shared__ float Xs[8192];
    int mt = blockIdx.x >> 1, ks = blockIdx.x & 1;   // grid 24
    stage_linear((const float*)g_query[par1] + ks * 8192, Xs);
    __syncthreads();
    gemm_core(W1ih + ks * 256, 512, g_gi1p[ks], mt * 128, Xs);
}

// ---------------- GRU gate combine ----------------
__global__ __launch_bounds__(256) void k_comb(
    int layer, int par, const float* __restrict__ bih, const float* __restrict__ bhh)
{
    int idx = blockIdx.x * 256 + threadIdx.x;   // 16384
    int j = idx >> 5, b = idx & 31;
    int o_r = j * 32 + b, o_z = (j + 512) * 32 + b, o_n = (j + 1024) * 32 + b;
    float gir, giz, gin_, ghr, ghz, ghn, hp;
    if (layer == 0) {
        gir  = g_gi0p[0][o_r] + g_gi0p[1][o_r] + g_gi0p[2][o_r] + g_gi0p[3][o_r];
        giz  = g_gi0p[0][o_z] + g_gi0p[1][o_z] + g_gi0p[2][o_z] + g_gi0p[3][o_z];
        gin_ = g_gi0p[0][o_n] + g_gi0p[1][o_n] + g_gi0p[2][o_n] + g_gi0p[3][o_n];
        ghr = g_gh0p[0][o_r] + g_gh0p[1][o_r];
        ghz = g_gh0p[0][o_z] + g_gh0p[1][o_z];
        ghn = g_gh0p[0][o_n] + g_gh0p[1][o_n];
        hp = g_query[par][j * 32 + b];
    } else {
        gir  = g_gi1p[0][o_r] + g_gi1p[1][o_r];
        giz  = g_gi1p[0][o_z] + g_gi1p[1][o_z];
        gin_ = g_gi1p[0][o_n] + g_gi1p[1][o_n];
        ghr = g_gh1p[0][o_r] + g_gh1p[1][o_r];
        ghz = g_gh1p[0][o_z] + g_gh1p[1][o_z];
        ghn = g_gh1p[0][o_n] + g_gh1p[1][o_n];
        hp = g_query[par][(512 + j) * 32 + b];
    }
    gir += bih[j];         ghr += bhh[j];
    giz += bih[j + 512];   ghz += bhh[j + 512];
    gin_ += bih[j + 1024]; ghn += bhh[j + 1024];
    float r = 1.f / (1.f + expf(-(gir + ghr)));
    float z = 1.f / (1.f + expf(-(giz + ghz)));
    float n = tanhf(gin_ + r * ghn);
    float h = (1.f - z) * n + z * hp;
    int off = layer ? 512 : 0;
    g_query[par ^ 1][(off + j) * 32 + b] = h;
}

// ---------------- logits + softmax partials ----------------
__global__ __launch_bounds__(128) void k_logits(
    const float* __restrict__ outW, const float* __restrict__ outb, int parN)
{
    __shared__ float Xs[8192];
    int tid = threadIdx.x;
    int bt = tid & 3, mt = tid >> 2;
    int b0 = bt * 8;
    int v0 = blockIdx.x * 128;   // grid 250
    ull acc[4][4];
    #pragma unroll
    for (int i = 0; i < 4; i++)
        #pragma unroll
        for (int j = 0; j < 4; j++) acc[i][j] = 0ULL;

    const float* h1T = (const float*)g_query[parN] + 512 * 32;
    for (int ck = 0; ck < 2; ck++) {
        if (ck) __syncthreads();
        stage_linear(h1T + ck * 8192, Xs);
        __syncthreads();
        const float* wr0 = outW + (size_t)(v0 + mt) * 512 + ck * 256;
        for (int kk = 0; kk < 256; kk += 4) {
            float4 w[4];
            #pragma unroll
            for (int i = 0; i < 4; i++)
                w[i] = *(const float4*)(wr0 + (size_t)i * 32 * 512 + kk);
            #pragma unroll
            for (int c = 0; c < 4; c++) {
                ull xp[4];
                #pragma unroll
                for (int j = 0; j < 4; j++)
                    xp[j] = *(const ull*)&Xs[(kk + c) * 32 + b0 + 2 * j];
                #pragma unroll
                for (int i = 0; i < 4; i++) {
                    const float* wf = reinterpret_cast<const float*>(&w[i]);
                    ull wd = pk2(wf[c], wf[c]);
                    #pragma unroll
                    for (int j = 0; j < 4; j++) acc[i][j] = fma2(wd, xp[j], acc[i][j]);
                }
            }
        }
    }
    float lv[8][4];
    #pragma unroll
    for (int i = 0; i < 4; i++) {
        int v = v0 + mt + i * 32;
        float bb = outb[v];
        #pragma unroll
        for (int j = 0; j < 4; j++) {
            float lo, hi; upk(acc[i][j], lo, hi);
            lv[2 * j][i] = lo + bb; lv[2 * j + 1][i] = hi + bb;
            g_logits[(size_t)(b0 + 2 * j) * V_ + v]     = lo + bb;
            g_logits[(size_t)(b0 + 2 * j + 1) * V_ + v] = hi + bb;
        }
    }
    __syncthreads();
    // per-(b, block) softmax partials: max, argmax (first-idx tie), sum exp
    float* sm_m = Xs;
    float* sm_s = Xs + 1024;
    int*   sm_i = (int*)(Xs + 2048);
    #pragma unroll
    for (int jj = 0; jj < 8; jj++) {
        int b = b0 + jj;
        float m = lv[jj][0]; int id = v0 + mt;
        #pragma unroll
        for (int i = 1; i < 4; i++) {
            float x = lv[jj][i];
            if (x > m) { m = x; id = v0 + mt + i * 32; }
        }
        float s = 0.f;
        #pragma unroll
        for (int i = 0; i < 4; i++) s += __expf(lv[jj][i] - m);
        sm_m[b * 32 + mt] = m; sm_s[b * 32 + mt] = s; sm_i[b * 32 + mt] = id;
    }
    __syncthreads();
    if (tid < 32) {
        int b = tid;
        float m = sm_m[b * 32], s = sm_s[b * 32];
        int id = sm_i[b * 32];
        for (int q = 1; q < 32; q++) {
            float mq = sm_m[b * 32 + q], sq = sm_s[b * 32 + q];
            int iq = sm_i[b * 32 + q];
            if (mq > m || (mq == m && iq < id)) {
                s = s * __expf(m - mq) + sq; m = mq; id = iq;
            } else {
                s += sq * __expf(mq - m);
            }
        }
        g_pm[b * 250 + blockIdx.x] = m;
        g_ps[b * 250 + blockIdx.x] = s;
        g_pi[b * 250 + blockIdx.x] = id;
    }
}

// ---------------- smwrite: every block redundantly reduces partials, writes slice ----------------
__global__ __launch_bounds__(256) void k_smwrite(float* __restrict__ lp, int t)
{
    int b = blockIdx.x >> 3, c = blockIdx.x & 7;   // grid 256
    int tid = threadIdx.x;
    __shared__ float rm[256], rs[256];
    __shared__ int ri[256];
    float m = -1e30f, s = 0.f; int id = 0x7fffffff;
    if (tid < 250) { m = g_pm[b * 250 + tid]; s = g_ps[b * 250 + tid]; id = g_pi[b * 250 + tid]; }
    rm[tid] = m; rs[tid] = s; ri[tid] = id;
    __syncthreads();
    for (int o = 128; o; o >>= 1) {
        if (tid < o) {
            float mq = rm[tid + o], sq = rs[tid + o];
            int iq = ri[tid + o];
            float mm = rm[tid];
            if (mq > mm || (mq == mm && iq < ri[tid])) {
                rs[tid] = rs[tid] * __expf(mm - mq) + sq; rm[tid] = mq; ri[tid] = iq;
            } else {
                rs[tid] += sq * __expf(mq - mm);
            }
        }
        __syncthreads();
    }
    float lse = logf(rs[0]) + rm[0];
    if (c == 0 && tid == 0) g_tok[b] = ri[0];

    const float* lg = g_logits + (size_t)b * V_;
    float* o = lp + ((size_t)b * T_ + t) * V_;
    for (int v = c * 4000 + tid; v < (c + 1) * 4000; v += 256)
        o[v] = lg[v] - lse;
}

// ---------------- final hidden out ----------------
__global__ void k_hidout(float* __restrict__ hid) {
    int idx = blockIdx.x * 256 + threadIdx.x;   // 32768
    int row = idx >> 5, b = idx & 31;
    int l = row >> 9, h = row & 511;
    hid[((size_t)l * 32 + b) * 512 + h] = g_query[0][row * 32 + b];
}

// ---------------- launcher (single stream, no events) ----------------
extern "C" void kernel_launch(void* const* d_in, const int* in_sizes, int n_in,
                              void* d_out, int out_size)
{
    const float* enc  = (const float*)d_in[0];
    const float* ehid = (const float*)d_in[1];
    const float* emb  = (const float*)d_in[3];
    const float* Wa   = (const float*)d_in[4];
    const float* ba   = (const float*)d_in[5];
    const float* Ua   = (const float*)d_in[6];
    const float* bua  = (const float*)d_in[7];
    const float* Va   = (const float*)d_in[8];
    const float* bva  = (const float*)d_in[9];
    const float* W0ih = (const float*)d_in[10];
    const float* W0hh = (const float*)d_in[11];
    const float* b0ih = (const float*)d_in[12];
    const float* b0hh = (const float*)d_in[13];
    const float* W1ih = (const float*)d_in[14];
    const float* W1hh = (const float*)d_in[15];
    const float* b1ih = (const float*)d_in[16];
    const float* b1hh = (const float*)d_in[17];
    const float* outW = (const float*)d_in[18];
    const float* outb = (const float*)d_in[19];

    float* out = (float*)d_out;
    const long long NLP  = (long long)B_ * T_ * V_;
    const long long NHID = 2LL * B_ * H_;
    const long long NATT = (long long)B_ * T_ * S_;
    bool full = (long long)out_size >= NLP + NHID + NATT;
    float* lp   = out;
    float* hid  = full ? out + NLP : nullptr;
    float* attn = full ? out + NLP + NHID : nullptr;

    k_init<<<128, 256>>>(ehid);
    k_ukeys<<<256, 256>>>(enc, Ua, bua);

    for (int t = 0; t < T_; t++) {
        int p = t & 1;
        k_q<<<16, 128>>>(Wa, p);
        k_scores<<<256, 128>>>(Va, ba, bva);
        k_attn2<<<32, 256>>>(enc, attn, t);
        k_gemmA<<<96, 128>>>(W0ih, emb, W0hh, W1hh, p);
        k_comb<<<64, 256>>>(0, p, b0ih, b0hh);
        k_gi1<<<24, 128>>>(W1ih, p ^ 1);
        k_comb<<<64, 256>>>(1, p, b1ih, b1hh);
        k_logits<<<250, 128>>>(outW, outb, p ^ 1);
        k_smwrite<<<256, 256>>>(lp, t);
    }
    if (hid) k_hidout<<<128, 256>>>(hid);
}